// round 7
// baseline (speedup 1.0000x reference)
#include <cuda_runtime.h>
#include <cstdint>

// ---------------------------------------------------------------------------
// FB_Seg: gather features at (r,c) coords from 3 CHW maps, run small MLP.
// Strategy:
//   1. Detect coord dtype (int64 vs int32) on device.
//   2. Counting-sort points by key = (b, r, c>>3) for L2 locality of gathers.
//   3. Precompute fused weights: wf = w_lin @ w1[0:64,:], b_eff = b_lin@w1_top + b1.
//   4. Fused gather + MLP kernel, fp32 with packed f32x2 FMA, weights in smem.
// ---------------------------------------------------------------------------

#define HWSZ (512*512)
#define WID   512
#define NPTS  120000
#define NTOT  240000
#define NLID  100000
#define NBINS 65536           // 2 batches * 512 rows * 64 col-octets

// smem layout offsets (in floats)
#define OF_WF   0             // 128x64 fused weights
#define OF_W1B  8192          // w1 rows 64..127 (64x64)
#define OF_W2   12288         // 64x32
#define OF_W3   14336         // 32x16
#define OF_W4   14848         // 16
#define OF_BEFF 14864         // 64
#define OF_B2   14928         // 32
#define OF_B3   14960         // 16
#define OF_B4   14976         // 1
#define SMEM_FLOATS 14980
#define SMEM_BYTES  (SMEM_FLOATS*4)

__device__ float              g_wf[8192];
__device__ float              g_beff[64];
__device__ unsigned int       g_cnt[NBINS];
__device__ unsigned int       g_off[NBINS];
__device__ unsigned long long g_sorted[NTOT];
__device__ int                g_is64;

// ---------------- packed f32x2 helpers (sm_100+) ---------------------------
__device__ __forceinline__ unsigned long long fma2(unsigned long long a,
                                                   unsigned long long b,
                                                   unsigned long long c) {
    unsigned long long d;
    asm("fma.rn.f32x2 %0, %1, %2, %3;" : "=l"(d) : "l"(a), "l"(b), "l"(c));
    return d;
}
__device__ __forceinline__ unsigned long long bcast2(float v) {
    unsigned long long d;
    unsigned int vi = __float_as_uint(v);
    asm("mov.b64 %0, {%1, %1};" : "=l"(d) : "r"(vi));
    return d;
}
__device__ __forceinline__ float2 unpack2(unsigned long long a) {
    unsigned int lo, hi;
    asm("mov.b64 {%0, %1}, %2;" : "=r"(lo), "=r"(hi) : "l"(a));
    return make_float2(__uint_as_float(lo), __uint_as_float(hi));
}

__device__ __forceinline__ float gelu_exact(float x) {
    return 0.5f * x * (1.0f + erff(x * 0.70710678118654752f));
}

// ---------------- coordinate fetch (dtype-agnostic) ------------------------
__device__ __forceinline__ void load_rc(const void* lidar, const void* radar,
                                        int is64, int b, int p,
                                        int& r, int& c) {
    const void* src;
    long long base;
    if (p < NLID) { src = lidar; base = ((long long)b * NLID + p) * 3; }
    else          { src = radar; base = ((long long)b * 20000 + (p - NLID)) * 3; }
    if (is64) {
        const long long* q = (const long long*)src + base;
        r = (int)q[1]; c = (int)q[2];
    } else {
        const int* q = (const int*)src + base;
        r = q[1]; c = q[2];
    }
}

// ---------------- small kernels -------------------------------------------
__global__ __launch_bounds__(32)
void detect_kernel(const unsigned int* lid_u32) {
    if (threadIdx.x == 0) {
        int all0 = 1;
        for (int k = 0; k < 32; k++)
            if (lid_u32[2 * k + 1] != 0u) all0 = 0;
        g_is64 = all0;   // int64 little-endian high words of values 0..511 are 0
    }
}

__global__ __launch_bounds__(256)
void zero_kernel() {
    int i = blockIdx.x * blockDim.x + threadIdx.x;
    if (i < NBINS) g_cnt[i] = 0u;
}

__global__ __launch_bounds__(256)
void prep_weights(const float* __restrict__ w_lin,
                  const float* __restrict__ b_lin,
                  const float* __restrict__ w1,
                  const float* __restrict__ b1) {
    int idx = blockIdx.x * blockDim.x + threadIdx.x;
    if (idx < 8192) {
        int i = idx >> 6, j = idx & 63;
        float s = 0.0f;
        #pragma unroll 8
        for (int k = 0; k < 64; k++)
            s = fmaf(w_lin[i * 64 + k], w1[k * 64 + j], s);
        g_wf[idx] = s;
    }
    if (idx < 64) {
        float s = b1[idx];
        for (int k = 0; k < 64; k++)
            s = fmaf(b_lin[k], w1[k * 64 + idx], s);
        g_beff[idx] = s;
    }
}

__global__ __launch_bounds__(256)
void hist_kernel(const void* lidar, const void* radar) {
    int g = blockIdx.x * blockDim.x + threadIdx.x;
    if (g >= NTOT) return;
    int is64 = g_is64;
    int b = g / NPTS, p = g - b * NPTS;
    int r, c;
    load_rc(lidar, radar, is64, b, p, r, c);
    unsigned int key = ((unsigned)b << 15) | ((unsigned)r << 6) | ((unsigned)c >> 3);
    atomicAdd(&g_cnt[key], 1u);
}

// 256 threads; each owns 256 consecutive bins. Two sequential passes over
// g_cnt (register-light) with a 256-wide shared Hillis-Steele scan between.
__global__ __launch_bounds__(256)
void scan_kernel() {
    __shared__ unsigned int ssum[256];
    int t = threadIdx.x;
    int base_i = t * 256;

    unsigned int run = 0;
    for (int k = 0; k < 256; k++) run += g_cnt[base_i + k];
    ssum[t] = run;
    __syncthreads();

    for (int off = 1; off < 256; off <<= 1) {
        unsigned int v = (t >= off) ? ssum[t - off] : 0u;
        __syncthreads();
        ssum[t] += v;
        __syncthreads();
    }
    unsigned int base = (t == 0) ? 0u : ssum[t - 1];

    for (int k = 0; k < 256; k++) {
        g_off[base_i + k] = base;
        base += g_cnt[base_i + k];
    }
}

__global__ __launch_bounds__(256)
void scatter_kernel(const void* lidar, const void* radar) {
    int g = blockIdx.x * blockDim.x + threadIdx.x;
    if (g >= NTOT) return;
    int is64 = g_is64;
    int b = g / NPTS, p = g - b * NPTS;
    int r, c;
    load_rc(lidar, radar, is64, b, p, r, c);
    unsigned int key = ((unsigned)b << 15) | ((unsigned)r << 6) | ((unsigned)c >> 3);
    unsigned int pos = atomicAdd(&g_off[key], 1u);
    g_sorted[pos] = (unsigned long long)p
                  | ((unsigned long long)r << 17)
                  | ((unsigned long long)c << 26);
}

// ---------------- main fused gather + MLP ----------------------------------
__global__ __launch_bounds__(256)
void main_kernel(const float* __restrict__ pc0,
                 const float* __restrict__ pc1,
                 const float* __restrict__ flm,
                 const float* __restrict__ w1,
                 const float* __restrict__ w2,
                 const float* __restrict__ b2,
                 const float* __restrict__ w3,
                 const float* __restrict__ b3,
                 const float* __restrict__ w4,
                 const float* __restrict__ b4,
                 float* __restrict__ out) {
    extern __shared__ float s[];
    int tid = threadIdx.x;

    // stage weights into smem
    for (int t = tid; t < 8192; t += 256) s[OF_WF + t]  = g_wf[t];
    for (int t = tid; t < 4096; t += 256) s[OF_W1B + t] = w1[4096 + t];
    for (int t = tid; t < 2048; t += 256) s[OF_W2 + t]  = w2[t];
    for (int t = tid; t < 512;  t += 256) s[OF_W3 + t]  = w3[t];
    if (tid < 16) s[OF_W4 + tid]   = w4[tid];
    if (tid < 64) s[OF_BEFF + tid] = g_beff[tid];
    if (tid < 32) s[OF_B2 + tid]   = b2[tid];
    if (tid < 16) s[OF_B3 + tid]   = b3[tid];
    if (tid == 0) s[OF_B4]         = b4[0];
    __syncthreads();

    int g = blockIdx.x * 256 + tid;
    if (g >= NTOT) return;

    unsigned long long e = g_sorted[g];
    int p = (int)(e & 0x1FFFFULL);
    int r = (int)((e >> 17) & 511ULL);
    int c = (int)((e >> 26) & 511ULL);
    int b = (g >= NPTS) ? 1 : 0;

    size_t base = (size_t)b * 64 * HWSZ + (size_t)r * WID + (size_t)c;
    const float* m0 = pc0 + base;
    const float* m1 = pc1 + base;
    const float* mf = flm + base;

    // ---- layer 1 (fused): acc = b_eff + f0*wf[0:64] + f1*wf[64:128] + ff*w1b
    unsigned long long acc[32];
    {
        const unsigned long long* bb = (const unsigned long long*)(s + OF_BEFF);
        #pragma unroll
        for (int k = 0; k < 32; k++) acc[k] = bb[k];
    }
    const unsigned long long* WF  = (const unsigned long long*)(s + OF_WF);
    const unsigned long long* W1B = (const unsigned long long*)(s + OF_W1B);

    #pragma unroll 4
    for (int i = 0; i < 64; i++) {
        unsigned long long vv = bcast2(m0[(size_t)i * HWSZ]);
        const ulonglong2* wr = (const ulonglong2*)(WF + i * 32);
        #pragma unroll
        for (int o = 0; o < 16; o++) {
            ulonglong2 w = wr[o];
            acc[2 * o]     = fma2(vv, w.x, acc[2 * o]);
            acc[2 * o + 1] = fma2(vv, w.y, acc[2 * o + 1]);
        }
    }
    #pragma unroll 4
    for (int i = 0; i < 64; i++) {
        unsigned long long vv = bcast2(m1[(size_t)i * HWSZ]);
        const ulonglong2* wr = (const ulonglong2*)(WF + (64 + i) * 32);
        #pragma unroll
        for (int o = 0; o < 16; o++) {
            ulonglong2 w = wr[o];
            acc[2 * o]     = fma2(vv, w.x, acc[2 * o]);
            acc[2 * o + 1] = fma2(vv, w.y, acc[2 * o + 1]);
        }
    }
    #pragma unroll 4
    for (int i = 0; i < 64; i++) {
        unsigned long long vv = bcast2(mf[(size_t)i * HWSZ]);
        const ulonglong2* wr = (const ulonglong2*)(W1B + i * 32);
        #pragma unroll
        for (int o = 0; o < 16; o++) {
            ulonglong2 w = wr[o];
            acc[2 * o]     = fma2(vv, w.x, acc[2 * o]);
            acc[2 * o + 1] = fma2(vv, w.y, acc[2 * o + 1]);
        }
    }

    float h1[64];
    #pragma unroll
    for (int k = 0; k < 32; k++) {
        float2 t = unpack2(acc[k]);
        h1[2 * k]     = gelu_exact(t.x);
        h1[2 * k + 1] = gelu_exact(t.y);
    }

    // ---- layer 2: 64 -> 32
    unsigned long long a2[16];
    {
        const unsigned long long* bb = (const unsigned long long*)(s + OF_B2);
        #pragma unroll
        for (int k = 0; k < 16; k++) a2[k] = bb[k];
    }
    const unsigned long long* W2 = (const unsigned long long*)(s + OF_W2);
    #pragma unroll
    for (int i = 0; i < 64; i++) {
        unsigned long long vv = bcast2(h1[i]);
        const ulonglong2* wr = (const ulonglong2*)(W2 + i * 16);
        #pragma unroll
        for (int o = 0; o < 8; o++) {
            ulonglong2 w = wr[o];
            a2[2 * o]     = fma2(vv, w.x, a2[2 * o]);
            a2[2 * o + 1] = fma2(vv, w.y, a2[2 * o + 1]);
        }
    }
    float h2[32];
    #pragma unroll
    for (int k = 0; k < 16; k++) {
        float2 t = unpack2(a2[k]);
        h2[2 * k]     = gelu_exact(t.x);
        h2[2 * k + 1] = gelu_exact(t.y);
    }

    // ---- layer 3: 32 -> 16
    unsigned long long a3[8];
    {
        const unsigned long long* bb = (const unsigned long long*)(s + OF_B3);
        #pragma unroll
        for (int k = 0; k < 8; k++) a3[k] = bb[k];
    }
    const unsigned long long* W3 = (const unsigned long long*)(s + OF_W3);
    #pragma unroll
    for (int i = 0; i < 32; i++) {
        unsigned long long vv = bcast2(h2[i]);
        const ulonglong2* wr = (const ulonglong2*)(W3 + i * 8);
        #pragma unroll
        for (int o = 0; o < 4; o++) {
            ulonglong2 w = wr[o];
            a3[2 * o]     = fma2(vv, w.x, a3[2 * o]);
            a3[2 * o + 1] = fma2(vv, w.y, a3[2 * o + 1]);
        }
    }
    float h3[16];
    #pragma unroll
    for (int k = 0; k < 8; k++) {
        float2 t = unpack2(a3[k]);
        h3[2 * k]     = gelu_exact(t.x);
        h3[2 * k + 1] = gelu_exact(t.y);
    }

    // ---- layer 4: 16 -> 1, sigmoid
    float z = s[OF_B4];
    #pragma unroll
    for (int i = 0; i < 16; i++) z = fmaf(h3[i], s[OF_W4 + i], z);
    float sg = 1.0f / (1.0f + expf(-z));

    out[(size_t)b * NPTS + p] = sg;
}

// ---------------------------------------------------------------------------
extern "C" void kernel_launch(void* const* d_in, const int* in_sizes, int n_in,
                              void* d_out, int out_size) {
    const float* pc0   = (const float*)d_in[0];
    const float* pc1   = (const float*)d_in[1];
    const float* flm   = (const float*)d_in[2];
    const void*  lidar = d_in[3];
    const void*  radar = d_in[4];
    const float* w_lin = (const float*)d_in[5];
    const float* b_lin = (const float*)d_in[6];
    const float* w1    = (const float*)d_in[7];
    const float* b1    = (const float*)d_in[8];
    const float* w2    = (const float*)d_in[9];
    const float* b2    = (const float*)d_in[10];
    const float* w3    = (const float*)d_in[11];
    const float* b3    = (const float*)d_in[12];
    const float* w4    = (const float*)d_in[13];
    const float* b4    = (const float*)d_in[14];
    float* out = (float*)d_out;

    cudaFuncSetAttribute(main_kernel,
                         cudaFuncAttributeMaxDynamicSharedMemorySize, SMEM_BYTES);

    detect_kernel<<<1, 32>>>((const unsigned int*)lidar);
    zero_kernel<<<NBINS / 256, 256>>>();
    prep_weights<<<32, 256>>>(w_lin, b_lin, w1, b1);
    hist_kernel<<<(NTOT + 255) / 256, 256>>>(lidar, radar);
    scan_kernel<<<1, 256>>>();
    scatter_kernel<<<(NTOT + 255) / 256, 256>>>(lidar, radar);
    main_kernel<<<(NTOT + 255) / 256, 256, SMEM_BYTES>>>(
        pc0, pc1, flm, w1, w2, b2, w3, b3, w4, b4, out);
}

// round 8
// speedup vs baseline: 1.1013x; 1.1013x over previous
#include <cuda_runtime.h>
#include <cstdint>

// ---------------------------------------------------------------------------
// FB_Seg: gather features at (r,c) coords from 3 CHW maps, run small MLP.
//   1. Detect coord dtype (int64 vs int32) on device.
//   2. Counting-sort points by key = (b, r, c>>3) for L2 locality of gathers.
//   3. Fuse first linear into layer 1: wf = w_lin @ w1_top, b_eff.
//   4. Main kernel: 2 threads per point (32 layer-1 outputs each) -> ~85 regs
//      -> 3 CTAs/SM (24 warps). f32x2 packed FMA, weights in smem.
// ---------------------------------------------------------------------------

#define HWSZ (512*512)
#define WID   512
#define NPTS  120000
#define NTOT  240000
#define NLID  100000
#define NBINS 65536           // 2 batches * 512 rows * 64 col-octets

// smem layout offsets (in floats)
#define OF_WF   0             // 128x64 fused weights
#define OF_W1B  8192          // w1 rows 64..127 (64x64)
#define OF_W2   12288         // 64x32
#define OF_W3   14336         // 32x16
#define OF_W4   14848         // 16
#define OF_BEFF 14864         // 64
#define OF_B2   14928         // 32
#define OF_B3   14960         // 16
#define OF_B4   14976         // 1
#define SMEM_FLOATS 14980
#define SMEM_BYTES  (SMEM_FLOATS*4)

__device__ float              g_wf[8192];
__device__ float              g_beff[64];
__device__ unsigned int       g_cnt[NBINS];
__device__ unsigned int       g_off[NBINS];
__device__ unsigned int       g_blk[256];
__device__ unsigned int       g_blkoff[256];
__device__ unsigned long long g_sorted[NTOT];
__device__ int                g_is64;

// ---------------- packed f32x2 helpers (sm_100+) ---------------------------
__device__ __forceinline__ unsigned long long fma2(unsigned long long a,
                                                   unsigned long long b,
                                                   unsigned long long c) {
    unsigned long long d;
    asm("fma.rn.f32x2 %0, %1, %2, %3;" : "=l"(d) : "l"(a), "l"(b), "l"(c));
    return d;
}
__device__ __forceinline__ unsigned long long bcast2(float v) {
    unsigned long long d;
    unsigned int vi = __float_as_uint(v);
    asm("mov.b64 %0, {%1, %1};" : "=l"(d) : "r"(vi));
    return d;
}
__device__ __forceinline__ float2 unpack2(unsigned long long a) {
    unsigned int lo, hi;
    asm("mov.b64 {%0, %1}, %2;" : "=r"(lo), "=r"(hi) : "l"(a));
    return make_float2(__uint_as_float(lo), __uint_as_float(hi));
}

__device__ __forceinline__ float gelu_exact(float x) {
    return 0.5f * x * (1.0f + erff(x * 0.70710678118654752f));
}

// ---------------- coordinate fetch (dtype-agnostic) ------------------------
__device__ __forceinline__ void load_rc(const void* lidar, const void* radar,
                                        int is64, int b, int p,
                                        int& r, int& c) {
    const void* src;
    long long base;
    if (p < NLID) { src = lidar; base = ((long long)b * NLID + p) * 3; }
    else          { src = radar; base = ((long long)b * 20000 + (p - NLID)) * 3; }
    if (is64) {
        const long long* q = (const long long*)src + base;
        r = (int)q[1]; c = (int)q[2];
    } else {
        const int* q = (const int*)src + base;
        r = q[1]; c = q[2];
    }
}

// ---------------- small kernels -------------------------------------------
// zero histogram + dtype detect (merged)
__global__ __launch_bounds__(256)
void init_kernel(const unsigned int* lid_u32) {
    int i = blockIdx.x * blockDim.x + threadIdx.x;
    if (i < NBINS) g_cnt[i] = 0u;
    if (i == 0) {
        int all0 = 1;
        for (int k = 0; k < 32; k++)
            if (lid_u32[2 * k + 1] != 0u) all0 = 0;
        g_is64 = all0;   // int64 LE high words of values 0..511 are 0
    }
}

__global__ __launch_bounds__(256)
void prep_weights(const float* __restrict__ w_lin,
                  const float* __restrict__ b_lin,
                  const float* __restrict__ w1,
                  const float* __restrict__ b1) {
    int idx = blockIdx.x * blockDim.x + threadIdx.x;
    if (idx < 8192) {
        int i = idx >> 6, j = idx & 63;
        float s = 0.0f;
        #pragma unroll 8
        for (int k = 0; k < 64; k++)
            s = fmaf(w_lin[i * 64 + k], w1[k * 64 + j], s);
        g_wf[idx] = s;
    }
    if (idx < 64) {
        float s = b1[idx];
        for (int k = 0; k < 64; k++)
            s = fmaf(b_lin[k], w1[k * 64 + idx], s);
        g_beff[idx] = s;
    }
}

__global__ __launch_bounds__(256)
void hist_kernel(const void* lidar, const void* radar) {
    int g = blockIdx.x * blockDim.x + threadIdx.x;
    if (g >= NTOT) return;
    int is64 = g_is64;
    int b = g / NPTS, p = g - b * NPTS;
    int r, c;
    load_rc(lidar, radar, is64, b, p, r, c);
    unsigned int key = ((unsigned)b << 15) | ((unsigned)r << 6) | ((unsigned)c >> 3);
    atomicAdd(&g_cnt[key], 1u);
}

// ---- parallel exclusive scan over 65536 bins: 3 small kernels --------------
__global__ __launch_bounds__(256)
void scan1_kernel() {
    __shared__ unsigned int ssum[256];
    int t = threadIdx.x;
    int i = blockIdx.x * 256 + t;
    unsigned int c = g_cnt[i];
    ssum[t] = c;
    __syncthreads();
    for (int off = 1; off < 256; off <<= 1) {
        unsigned int v = (t >= off) ? ssum[t - off] : 0u;
        __syncthreads();
        ssum[t] += v;
        __syncthreads();
    }
    g_off[i] = ssum[t] - c;                 // exclusive within block
    if (t == 255) g_blk[blockIdx.x] = ssum[255];
}

__global__ __launch_bounds__(256)
void scan2_kernel() {
    __shared__ unsigned int ssum[256];
    int t = threadIdx.x;
    unsigned int c = g_blk[t];
    ssum[t] = c;
    __syncthreads();
    for (int off = 1; off < 256; off <<= 1) {
        unsigned int v = (t >= off) ? ssum[t - off] : 0u;
        __syncthreads();
        ssum[t] += v;
        __syncthreads();
    }
    g_blkoff[t] = ssum[t] - c;              // exclusive block base
}

__global__ __launch_bounds__(256)
void scan3_kernel() {
    int i = blockIdx.x * 256 + threadIdx.x;
    g_off[i] += g_blkoff[blockIdx.x];
}

__global__ __launch_bounds__(256)
void scatter_kernel(const void* lidar, const void* radar) {
    int g = blockIdx.x * blockDim.x + threadIdx.x;
    if (g >= NTOT) return;
    int is64 = g_is64;
    int b = g / NPTS, p = g - b * NPTS;
    int r, c;
    load_rc(lidar, radar, is64, b, p, r, c);
    unsigned int key = ((unsigned)b << 15) | ((unsigned)r << 6) | ((unsigned)c >> 3);
    unsigned int pos = atomicAdd(&g_off[key], 1u);
    g_sorted[pos] = (unsigned long long)p
                  | ((unsigned long long)r << 17)
                  | ((unsigned long long)c << 26);
}

// ---------------- main fused gather + MLP ----------------------------------
// 2 threads per point: lane pair (2k, 2k+1) shares one point; thread computes
// layer-1/2 columns [32h, 32h+32). Layer-2 is split-K + shfl_xor reduce;
// layers 3-4 computed redundantly by both lanes (tiny).
__global__ __launch_bounds__(256, 3)
void main_kernel(const float* __restrict__ pc0,
                 const float* __restrict__ pc1,
                 const float* __restrict__ flm,
                 const float* __restrict__ w1,
                 const float* __restrict__ w2,
                 const float* __restrict__ b2,
                 const float* __restrict__ w3,
                 const float* __restrict__ b3,
                 const float* __restrict__ w4,
                 const float* __restrict__ b4,
                 float* __restrict__ out) {
    extern __shared__ float s[];
    int tid = threadIdx.x;

    // stage weights into smem
    for (int t = tid; t < 8192; t += 256) s[OF_WF + t]  = g_wf[t];
    for (int t = tid; t < 4096; t += 256) s[OF_W1B + t] = w1[4096 + t];
    for (int t = tid; t < 2048; t += 256) s[OF_W2 + t]  = w2[t];
    for (int t = tid; t < 512;  t += 256) s[OF_W3 + t]  = w3[t];
    if (tid < 16) s[OF_W4 + tid]   = w4[tid];
    if (tid < 64) s[OF_BEFF + tid] = g_beff[tid];
    if (tid < 32) s[OF_B2 + tid]   = b2[tid];
    if (tid < 16) s[OF_B3 + tid]   = b3[tid];
    if (tid == 0) s[OF_B4]         = b4[0];
    __syncthreads();

    int g = blockIdx.x * 128 + (tid >> 1);   // point index (pair-shared)
    int h = tid & 1;                         // output half
    if (g >= NTOT) return;                   // grid is exact; kept for safety

    unsigned long long e = g_sorted[g];
    int p = (int)(e & 0x1FFFFULL);
    int r = (int)((e >> 17) & 511ULL);
    int c = (int)((e >> 26) & 511ULL);
    int b = (g >= NPTS) ? 1 : 0;

    size_t base = (size_t)b * 64 * HWSZ + (size_t)r * WID + (size_t)c;
    const float* m0 = pc0 + base;
    const float* m1 = pc1 + base;
    const float* mf = flm + base;

    int hoff = h << 5;                       // 0 or 32 columns

    // ---- layer 1 (fused), 32 outputs: acc = b_eff + f0*wf + f1*wf + ff*w1b
    unsigned long long acc[16];
    {
        const unsigned long long* bb =
            (const unsigned long long*)(s + OF_BEFF + hoff);
        #pragma unroll
        for (int k = 0; k < 16; k++) acc[k] = bb[k];
    }
    const float* WF  = s + OF_WF  + hoff;    // row stride 64
    const float* W1B = s + OF_W1B + hoff;

    #pragma unroll 2
    for (int i = 0; i < 64; i++) {
        unsigned long long vv = bcast2(m0[(size_t)i * HWSZ]);
        const ulonglong2* wr = (const ulonglong2*)(WF + i * 64);
        #pragma unroll
        for (int o = 0; o < 8; o++) {
            ulonglong2 w = wr[o];
            acc[2 * o]     = fma2(vv, w.x, acc[2 * o]);
            acc[2 * o + 1] = fma2(vv, w.y, acc[2 * o + 1]);
        }
    }
    #pragma unroll 2
    for (int i = 0; i < 64; i++) {
        unsigned long long vv = bcast2(m1[(size_t)i * HWSZ]);
        const ulonglong2* wr = (const ulonglong2*)(WF + (64 + i) * 64);
        #pragma unroll
        for (int o = 0; o < 8; o++) {
            ulonglong2 w = wr[o];
            acc[2 * o]     = fma2(vv, w.x, acc[2 * o]);
            acc[2 * o + 1] = fma2(vv, w.y, acc[2 * o + 1]);
        }
    }
    #pragma unroll 2
    for (int i = 0; i < 64; i++) {
        unsigned long long vv = bcast2(mf[(size_t)i * HWSZ]);
        const ulonglong2* wr = (const ulonglong2*)(W1B + i * 64);
        #pragma unroll
        for (int o = 0; o < 8; o++) {
            ulonglong2 w = wr[o];
            acc[2 * o]     = fma2(vv, w.x, acc[2 * o]);
            acc[2 * o + 1] = fma2(vv, w.y, acc[2 * o + 1]);
        }
    }

    float h1v[32];
    #pragma unroll
    for (int k = 0; k < 16; k++) {
        float2 t = unpack2(acc[k]);
        h1v[2 * k]     = gelu_exact(t.x);
        h1v[2 * k + 1] = gelu_exact(t.y);
    }

    // ---- layer 2: 64 -> 32, split-K across the lane pair.
    // This thread holds h1 rows [32h, 32h+32); accumulate partial a2 over
    // those rows, then butterfly-reduce with the partner lane.
    unsigned long long a2[16];
    if (h == 0) {
        const unsigned long long* bb = (const unsigned long long*)(s + OF_B2);
        #pragma unroll
        for (int k = 0; k < 16; k++) a2[k] = bb[k];
    } else {
        #pragma unroll
        for (int k = 0; k < 16; k++) a2[k] = 0ULL;
    }
    const float* W2 = s + OF_W2 + hoff * 32; // rows [32h..), 32 cols each
    #pragma unroll 2
    for (int i = 0; i < 32; i++) {
        unsigned long long vv = bcast2(h1v[i]);
        const ulonglong2* wr = (const ulonglong2*)(W2 + i * 32);
        #pragma unroll
        for (int o = 0; o < 8; o++) {
            ulonglong2 w = wr[o];
            a2[2 * o]     = fma2(vv, w.x, a2[2 * o]);
            a2[2 * o + 1] = fma2(vv, w.y, a2[2 * o + 1]);
        }
    }
    float h2v[32];
    #pragma unroll
    for (int k = 0; k < 16; k++) {
        float2 t = unpack2(a2[k]);
        t.x += __shfl_xor_sync(0xffffffffu, t.x, 1);
        t.y += __shfl_xor_sync(0xffffffffu, t.y, 1);
        h2v[2 * k]     = gelu_exact(t.x);
        h2v[2 * k + 1] = gelu_exact(t.y);
    }

    // ---- layer 3: 32 -> 16 (both lanes redundantly)
    unsigned long long a3[8];
    {
        const unsigned long long* bb = (const unsigned long long*)(s + OF_B3);
        #pragma unroll
        for (int k = 0; k < 8; k++) a3[k] = bb[k];
    }
    const float* W3 = s + OF_W3;
    #pragma unroll 2
    for (int i = 0; i < 32; i++) {
        unsigned long long vv = bcast2(h2v[i]);
        const ulonglong2* wr = (const ulonglong2*)(W3 + i * 16);
        #pragma unroll
        for (int o = 0; o < 4; o++) {
            ulonglong2 w = wr[o];
            a3[2 * o]     = fma2(vv, w.x, a3[2 * o]);
            a3[2 * o + 1] = fma2(vv, w.y, a3[2 * o + 1]);
        }
    }

    // ---- layer 4: 16 -> 1, sigmoid
    float z = s[OF_B4];
    #pragma unroll
    for (int k = 0; k < 8; k++) {
        float2 t = unpack2(a3[k]);
        float g3x = gelu_exact(t.x);
        float g3y = gelu_exact(t.y);
        z = fmaf(g3x, s[OF_W4 + 2 * k],     z);
        z = fmaf(g3y, s[OF_W4 + 2 * k + 1], z);
    }
    float sg = 1.0f / (1.0f + expf(-z));

    if (h == 0) out[(size_t)b * NPTS + p] = sg;
}

// ---------------------------------------------------------------------------
extern "C" void kernel_launch(void* const* d_in, const int* in_sizes, int n_in,
                              void* d_out, int out_size) {
    const float* pc0   = (const float*)d_in[0];
    const float* pc1   = (const float*)d_in[1];
    const float* flm   = (const float*)d_in[2];
    const void*  lidar = d_in[3];
    const void*  radar = d_in[4];
    const float* w_lin = (const float*)d_in[5];
    const float* b_lin = (const float*)d_in[6];
    const float* w1    = (const float*)d_in[7];
    const float* b1    = (const float*)d_in[8];
    const float* w2    = (const float*)d_in[9];
    const float* b2    = (const float*)d_in[10];
    const float* w3    = (const float*)d_in[11];
    const float* b3    = (const float*)d_in[12];
    const float* w4    = (const float*)d_in[13];
    const float* b4    = (const float*)d_in[14];
    float* out = (float*)d_out;

    cudaFuncSetAttribute(main_kernel,
                         cudaFuncAttributeMaxDynamicSharedMemorySize, SMEM_BYTES);

    init_kernel<<<NBINS / 256, 256>>>((const unsigned int*)lidar);
    prep_weights<<<32, 256>>>(w_lin, b_lin, w1, b1);
    hist_kernel<<<(NTOT + 255) / 256, 256>>>(lidar, radar);
    scan1_kernel<<<256, 256>>>();
    scan2_kernel<<<1, 256>>>();
    scan3_kernel<<<256, 256>>>();
    scatter_kernel<<<(NTOT + 255) / 256, 256>>>(lidar, radar);
    // 2 threads per point -> 128 points per 256-thread CTA
    main_kernel<<<(NTOT + 127) / 128, 256, SMEM_BYTES>>>(
        pc0, pc1, flm, w1, w2, b2, w3, b3, w4, b4, out);
}